// round 1
// baseline (speedup 1.0000x reference)
#include <cuda_runtime.h>

// Shapes are fixed by the problem definition.
#define Bv 2
#define Cv 3
#define Dv 128
#define Hv 192
#define Wv 192
#define PW (Wv + 1)   // padded row stride: 193 (== 1 mod 32 -> conflict-free both axes)

// ---------------------------------------------------------------------------
// Kernel 1: fused x-solve (along W) + y-solve (along H), one CTA per (b,c,d)
// slice of H*W contiguous floats. Slice lives in padded SMEM.
// ---------------------------------------------------------------------------
__global__ __launch_bounds__(192, 1)
void xy_solve_kernel(const float* __restrict__ in, float* __restrict__ out,
                     const float* __restrict__ ax, const float* __restrict__ bx,
                     const float* __restrict__ cx,
                     const float* __restrict__ ay, const float* __restrict__ by,
                     const float* __restrict__ cy)
{
    extern __shared__ float sm[];
    float* tile  = sm;                       // Hv * PW
    float* s_ax  = tile + Hv * PW;           // Wv
    float* s_iax = s_ax + Wv;                // Wv   (1/ax)
    float* s_bx  = s_iax + Wv;               // Wv-1
    float* s_cx  = s_bx + (Wv - 1);          // Wv-1
    float* s_ay  = s_cx + (Wv - 1);          // Hv
    float* s_iay = s_ay + Hv;                // Hv
    float* s_by  = s_iay + Hv;               // Hv-1
    float* s_cy  = s_by + (Hv - 1);          // Hv-1

    const int t = threadIdx.x;

    // Coefficients into SMEM (once per CTA).
    if (t < Wv)     { float a = ax[t]; s_ax[t] = a; s_iax[t] = 1.0f / a; }
    if (t < Wv - 1) { s_bx[t] = bx[t]; s_cx[t] = cx[t]; }
    if (t < Hv)     { float a = ay[t]; s_ay[t] = a; s_iay[t] = 1.0f / a; }
    if (t < Hv - 1) { s_by[t] = by[t]; s_cy[t] = cy[t]; }

    const float* g = in + (size_t)blockIdx.x * (Hv * Wv);

    // Coalesced load: thread t owns column t of each row; STS banks = (k*193+t)%32
    // -> consecutive per-thread, conflict-free.
    #pragma unroll 4
    for (int k = 0; k < Hv; k++)
        tile[k * PW + t] = g[k * Wv + t];
    __syncthreads();

    // ---- x-solve: thread t = row h = t --------------------------------------
    {
        float* row = tile + t * PW;
        float carry = row[0];
        #pragma unroll 8
        for (int i = 1; i < Wv; i++) {
            carry = fmaf(-s_cx[i - 1], carry, row[i]);
            row[i] = carry;
        }
        carry = carry * s_iax[Wv - 1];
        row[Wv - 1] = carry;
        #pragma unroll 8
        for (int i = Wv - 2; i >= 0; i--) {
            carry = (row[i] - s_bx[i] * carry) * s_iax[i];
            row[i] = carry;
        }
    }
    __syncthreads();

    // ---- y-solve: thread t = column w = t -----------------------------------
    {
        float carry = tile[t];
        #pragma unroll 8
        for (int i = 1; i < Hv; i++) {
            carry = fmaf(-s_cy[i - 1], carry, tile[i * PW + t]);
            tile[i * PW + t] = carry;
        }
        carry *= s_iay[Hv - 1];
        tile[(Hv - 1) * PW + t] = carry;
        #pragma unroll 8
        for (int i = Hv - 2; i >= 0; i--) {
            carry = (tile[i * PW + t] - s_by[i] * carry) * s_iay[i];
            tile[i * PW + t] = carry;
        }
    }
    __syncthreads();

    // Coalesced store.
    float* o = out + (size_t)blockIdx.x * (Hv * Wv);
    #pragma unroll 4
    for (int k = 0; k < Hv; k++)
        o[k * Wv + t] = tile[k * PW + t];
}

// ---------------------------------------------------------------------------
// Kernel 2: z-solve (along D), in-place on out. One CTA per (b,c,h) slab:
// D x W tile in SMEM, thread t owns w-column t end-to-end (no data-path syncs).
// ---------------------------------------------------------------------------
__global__ __launch_bounds__(192, 2)
void z_solve_kernel(float* __restrict__ io,
                    const float* __restrict__ az, const float* __restrict__ bz,
                    const float* __restrict__ cz)
{
    extern __shared__ float sm[];
    float* tile = sm;                        // Dv * Wv (no pad needed: threads vary w)
    float* s_a  = tile + Dv * Wv;            // Dv
    float* s_ia = s_a + Dv;                  // Dv
    float* s_b  = s_ia + Dv;                 // Dv-1
    float* s_c  = s_b + (Dv - 1);            // Dv-1

    const int t = threadIdx.x;

    if (t < Dv)     { float a = az[t]; s_a[t] = a; s_ia[t] = 1.0f / a; }
    if (t < Dv - 1) { s_b[t] = bz[t]; s_c[t] = cz[t]; }

    const int n  = blockIdx.x;       // over B*C*H
    const int h  = n % Hv;
    const int bc = n / Hv;
    float* g = io + (size_t)bc * (Dv * Hv * Wv) + (size_t)h * Wv;

    // Coalesced load of this thread's own column (192 contiguous floats per d).
    #pragma unroll 4
    for (int d = 0; d < Dv; d++)
        tile[d * Wv + t] = g[(size_t)d * (Hv * Wv) + t];
    __syncthreads();   // only for the coefficient arrays (loaded by t<128)

    float carry = tile[t];
    #pragma unroll 8
    for (int d = 1; d < Dv; d++) {
        carry = fmaf(-s_c[d - 1], carry, tile[d * Wv + t]);
        tile[d * Wv + t] = carry;
    }
    carry *= s_ia[Dv - 1];
    tile[(Dv - 1) * Wv + t] = carry;
    #pragma unroll 8
    for (int d = Dv - 2; d >= 0; d--) {
        carry = (tile[d * Wv + t] - s_b[d] * carry) * s_ia[d];
        tile[d * Wv + t] = carry;
    }

    // Thread wrote only its own column: no sync needed before store.
    #pragma unroll 4
    for (int d = 0; d < Dv; d++)
        g[(size_t)d * (Hv * Wv) + t] = tile[d * Wv + t];
}

// ---------------------------------------------------------------------------
extern "C" void kernel_launch(void* const* d_in, const int* in_sizes, int n_in,
                              void* d_out, int out_size)
{
    const float* field = (const float*)d_in[0];
    const float* ax = (const float*)d_in[1];
    const float* bx = (const float*)d_in[2];
    const float* cx = (const float*)d_in[3];
    const float* ay = (const float*)d_in[4];
    const float* by = (const float*)d_in[5];
    const float* cy = (const float*)d_in[6];
    const float* az = (const float*)d_in[7];
    const float* bz = (const float*)d_in[8];
    const float* cz = (const float*)d_in[9];
    float* out = (float*)d_out;

    const int smem_xy = (Hv * PW + 2 * Wv + 2 * (Wv - 1)
                                 + 2 * Hv + 2 * (Hv - 1)) * (int)sizeof(float);
    const int smem_z  = (Dv * Wv + 2 * Dv + 2 * (Dv - 1)) * (int)sizeof(float);

    // Opt-in to >48KB dynamic SMEM (host-side config, not a stream op; idempotent).
    cudaFuncSetAttribute(xy_solve_kernel,
                         cudaFuncAttributeMaxDynamicSharedMemorySize, smem_xy);
    cudaFuncSetAttribute(z_solve_kernel,
                         cudaFuncAttributeMaxDynamicSharedMemorySize, smem_z);

    xy_solve_kernel<<<Bv * Cv * Dv, 192, smem_xy>>>(field, out,
                                                    ax, bx, cx, ay, by, cy);
    z_solve_kernel<<<Bv * Cv * Hv, 192, smem_z>>>(out, az, bz, cz);
}

// round 5
// speedup vs baseline: 2.8141x; 2.8141x over previous
#include <cuda_runtime.h>

// Fixed shapes.
#define Bv 2
#define Cv 3
#define Dv 128
#define Hv 192
#define Wv 192
#define PW (Wv + 1)        // padded row stride 193 (==1 mod 32): conflict-free both axes
#define HW (Hv * Wv)

// ---------------------------------------------------------------------------
// Kernel 1: fused x-solve (W) + y-solve (H). One CTA per (b,c,d) slice.
// Chains are single-FFMA; final y-backward sweep streams directly to global.
// ---------------------------------------------------------------------------
__global__ __launch_bounds__(192, 1)
void xy_solve_kernel(const float* __restrict__ in, float* __restrict__ out,
                     const float* __restrict__ ax, const float* __restrict__ bx,
                     const float* __restrict__ cx,
                     const float* __restrict__ ay, const float* __restrict__ by,
                     const float* __restrict__ cy)
{
    extern __shared__ float sm[];
    float* tile  = sm;                       // Hv * PW
    float* s_cx  = tile + Hv * PW;           // Wv-1
    float* s_iax = s_cx + (Wv - 1);          // Wv
    float* s_fx  = s_iax + Wv;               // Wv-1  (bx / ax)
    float* s_cy  = s_fx + (Wv - 1);          // Hv-1
    float* s_iay = s_cy + (Hv - 1);          // Hv
    float* s_fy  = s_iay + Hv;               // Hv-1  (by / ay)

    const int t = threadIdx.x;

    // Coefficient prep (once per CTA).
    if (t < Wv)     { s_iax[t] = 1.0f / ax[t]; }
    if (t < Wv - 1) { s_cx[t] = cx[t]; s_fx[t] = bx[t] / ax[t]; }
    if (t < Hv)     { s_iay[t] = 1.0f / ay[t]; }
    if (t < Hv - 1) { s_cy[t] = cy[t]; s_fy[t] = by[t] / ay[t]; }

    // Vectorized coalesced load: float4 per thread, 4 rows per iteration.
    {
        const float4* g4 = (const float4*)(in + (size_t)blockIdx.x * HW);
        const int c4 = t % 48;         // float4 column 0..47
        const int r0 = t / 48;         // row-within-group 0..3
        #pragma unroll
        for (int it = 0; it < 48; it++) {
            const int k = it * 4 + r0;
            float4 v = g4[k * 48 + c4];
            float* d = tile + k * PW + c4 * 4;
            d[0] = v.x; d[1] = v.y; d[2] = v.z; d[3] = v.w;
        }
    }
    __syncthreads();

    // ---- x-solve: thread t owns row h = t -----------------------------------
    {
        float* row = tile + t * PW;
        float carry = row[0];
        #pragma unroll 16
        for (int i = 1; i < Wv; i++) {
            carry = fmaf(-s_cx[i - 1], carry, row[i]);   // pure FFMA chain
            row[i] = carry;
        }
        carry = carry * s_iax[Wv - 1];
        row[Wv - 1] = carry;
        #pragma unroll 16
        for (int i = Wv - 2; i >= 0; i--) {
            carry = fmaf(-s_fx[i], carry, row[i] * s_iax[i]);  // off-chain mul
            row[i] = carry;
        }
    }
    __syncthreads();

    // ---- y-solve: thread t owns column w = t --------------------------------
    {
        float carry = tile[t];
        #pragma unroll 16
        for (int i = 1; i < Hv; i++) {
            carry = fmaf(-s_cy[i - 1], carry, tile[i * PW + t]);
            tile[i * PW + t] = carry;
        }
        // Backward sweep streams results straight to global (coalesced rows).
        float* o = out + (size_t)blockIdx.x * HW;
        carry = carry * s_iay[Hv - 1];
        o[(Hv - 1) * Wv + t] = carry;
        #pragma unroll 16
        for (int i = Hv - 2; i >= 0; i--) {
            carry = fmaf(-s_fy[i], carry, tile[i * PW + t] * s_iay[i]);
            o[i * Wv + t] = carry;
        }
    }
}

// ---------------------------------------------------------------------------
// Kernel 2: z-solve (D), in-place on out. Thread t owns full column (b,c,:,h,t)
// in REGISTERS: no smem tile, 128-deep load MLP, FFMA-only chains, stores
// fused into the backward sweep.
// ---------------------------------------------------------------------------
__global__ __launch_bounds__(192, 2)
void z_solve_kernel(float* __restrict__ io,
                    const float* __restrict__ az, const float* __restrict__ bz,
                    const float* __restrict__ cz)
{
    __shared__ float s_c[Dv - 1];   // cz
    __shared__ float s_ia[Dv];      // 1/az
    __shared__ float s_f[Dv - 1];   // bz/az

    const int t = threadIdx.x;
    if (t < Dv)     { s_ia[t] = 1.0f / az[t]; }
    if (t < Dv - 1) { s_c[t] = cz[t]; s_f[t] = bz[t] / az[t]; }
    __syncthreads();

    const int n  = blockIdx.x;            // over B*C*H
    const int h  = n % Hv;
    const int bc = n / Hv;
    float* g = io + (size_t)bc * (Dv * HW) + (size_t)h * Wv + t;

    // Load entire column into registers (all LDGs independent -> deep MLP).
    float y[Dv];
    #pragma unroll
    for (int d = 0; d < Dv; d++)
        y[d] = g[(size_t)d * HW];

    // Forward sweep (register-resident, 1 FFMA per step).
    #pragma unroll
    for (int d = 1; d < Dv; d++)
        y[d] = fmaf(-s_c[d - 1], y[d - 1], y[d]);

    // Backward sweep fused with coalesced stores.
    float carry = y[Dv - 1] * s_ia[Dv - 1];
    g[(size_t)(Dv - 1) * HW] = carry;
    #pragma unroll
    for (int d = Dv - 2; d >= 0; d--) {
        carry = fmaf(-s_f[d], carry, y[d] * s_ia[d]);
        g[(size_t)d * HW] = carry;
    }
}

// ---------------------------------------------------------------------------
extern "C" void kernel_launch(void* const* d_in, const int* in_sizes, int n_in,
                              void* d_out, int out_size)
{
    const float* field = (const float*)d_in[0];
    const float* ax = (const float*)d_in[1];
    const float* bx = (const float*)d_in[2];
    const float* cx = (const float*)d_in[3];
    const float* ay = (const float*)d_in[4];
    const float* by = (const float*)d_in[5];
    const float* cy = (const float*)d_in[6];
    const float* az = (const float*)d_in[7];
    const float* bz = (const float*)d_in[8];
    const float* cz = (const float*)d_in[9];
    float* out = (float*)d_out;

    const int smem_xy = (Hv * PW + (Wv - 1) + Wv + (Wv - 1)
                                  + (Hv - 1) + Hv + (Hv - 1)) * (int)sizeof(float);

    cudaFuncSetAttribute(xy_solve_kernel,
                         cudaFuncAttributeMaxDynamicSharedMemorySize, smem_xy);

    xy_solve_kernel<<<Bv * Cv * Dv, 192, smem_xy>>>(field, out,
                                                    ax, bx, cx, ay, by, cy);
    z_solve_kernel<<<Bv * Cv * Hv, 192>>>(out, az, bz, cz);
}